// round 5
// baseline (speedup 1.0000x reference)
#include <cuda_runtime.h>
#include <cub/cub.cuh>
#include <cstdint>

namespace {
constexpr int BATCH = 8;
constexpr int NANCH = 262144;         // 2^18
constexpr int TOTAL = BATCH * NANCH;  // 2,097,152
constexpr int TOPK  = 6000;
constexpr int NOUT  = 1000;
constexpr int COLB  = (TOPK + 63) / 64;            // 94
constexpr float THR = 0.7f;
constexpr int TAIL_BITS = TOPK - (COLB - 1) * 64;  // 48
constexpr int HBINS = 32768;   // bucket = float_bits >> 15 (scores in (0,1) -> bits < 2^30)
constexpr int CAP   = 16384;   // per-batch candidate capacity (expected ~6400)
// sweep dynamic smem: diag[TOPK] u64 + rem[COLB] u64 + kept[NOUT] int + 2 ints
constexpr int SWEEP_SMEM = TOPK * 8 + COLB * 8 + NOUT * 4 + 16;
}

// -------- device-global scratch (no allocation allowed) ----------------------
__device__ int                g_hist[BATCH * HBINS];
__device__ int                g_thresh[BATCH];
__device__ int                g_cnt[BATCH];
__device__ unsigned long long g_cand  [BATCH * CAP];
__device__ unsigned long long g_sorted[BATCH * CAP];
__device__ int                g_segoff[BATCH + 1] =
    {0, CAP, 2*CAP, 3*CAP, 4*CAP, 5*CAP, 6*CAP, 7*CAP, 8*CAP};
__device__ __align__(16) float g_boxes[BATCH * TOPK * 4];
__device__ unsigned long long g_mask[(size_t)BATCH * TOPK * COLB];  // upper-tri valid
__device__ unsigned long long g_diag[BATCH * TOPK];
__device__ unsigned char      g_temp[16 * 1024 * 1024];             // cub temp

// -------- 1. per-batch histogram of score buckets ----------------------------
__global__ void hist_kernel(const float2* __restrict__ cls) {
    int g = blockIdx.x * blockDim.x + threadIdx.x;
    if (g >= TOTAL) return;
    float s = cls[g].y;                      // rpn_class[:,:,1], softmax > 0
    int bucket = (int)(__float_as_uint(s) >> 15);
    atomicAdd(&g_hist[(g >> 18) * HBINS + bucket], 1);
}

// -------- 2. find threshold bucket: largest T with count(bucket >= T) >= TOPK -
__global__ void thresh_kernel() {
    constexpr int BPT = HBINS / 256;  // 128 bins per thread
    int b = blockIdx.x;
    int t = threadIdx.x;
    __shared__ int lsum[256];
    __shared__ int suff[256];
    int base = b * HBINS + t * BPT;
    int s = 0;
    for (int i = 0; i < BPT; ++i) s += g_hist[base + i];
    lsum[t] = s;
    __syncthreads();
    if (t == 0) {
        int run = 0;
        for (int u = 255; u >= 0; --u) { suff[u] = run; run += lsum[u]; }
    }
    __syncthreads();
    int above = suff[t];
    if (above < TOPK && above + lsum[t] >= TOPK) {  // unique crossing thread
        int run = above;
        for (int i = BPT - 1; i >= 0; --i) {
            run += g_hist[base + i];
            if (run >= TOPK) { g_thresh[b] = t * BPT + i; break; }
        }
    }
}

// -------- 3. compact candidates with composite key ---------------------------
// key = (score_bits << 18) | (0x3FFFF - idx): descending sort => desc by score,
// ties broken by ascending index == jax.lax.top_k semantics.
__global__ void compact_kernel(const float2* __restrict__ cls) {
    int g = blockIdx.x * blockDim.x + threadIdx.x;
    if (g >= TOTAL) return;
    unsigned int bits = __float_as_uint(cls[g].y);
    int b = g >> 18;
    if ((int)(bits >> 15) >= __ldg(&g_thresh[b])) {
        int pos = atomicAdd(&g_cnt[b], 1);
        if (pos < CAP)
            g_cand[b * CAP + pos] =
                ((unsigned long long)bits << 18) |
                (unsigned long long)(0x3FFFF - (g & (NANCH - 1)));
    }
}

// -------- 4. gather top-6000, apply deltas, clip ------------------------------
__global__ void boxes_kernel(const float* __restrict__ rpn_bbox,
                             const float* __restrict__ anchors) {
    int t = blockIdx.x * blockDim.x + threadIdx.x;
    if (t >= BATCH * TOPK) return;
    int b = t / TOPK;
    int k = t - b * TOPK;
    unsigned long long key = g_sorted[b * CAP + k];
    int idx = 0x3FFFF - (int)(key & 0x3FFFFull);
    int src = (b * NANCH + idx) * 4;
    float4 a = *reinterpret_cast<const float4*>(anchors  + src);
    float4 d = *reinterpret_cast<const float4*>(rpn_bbox + src);
    float dy = d.x * 0.1f, dx = d.y * 0.1f;
    float dh = d.z * 0.2f, dw = d.w * 0.2f;
    float h = a.z - a.x;
    float w = a.w - a.y;
    float cy = a.x + 0.5f * h;
    float cx = a.y + 0.5f * w;
    cy = cy + dy * h;
    cx = cx + dx * w;
    h = h * expf(dh);
    w = w * expf(dw);
    float y1 = fminf(fmaxf(cy - 0.5f * h, 0.f), 1.f);
    float x1 = fminf(fmaxf(cx - 0.5f * w, 0.f), 1.f);
    float y2 = fminf(fmaxf(cy + 0.5f * h, 0.f), 1.f);
    float x2 = fminf(fmaxf(cx + 0.5f * w, 0.f), 1.f);
    reinterpret_cast<float4*>(g_boxes)[t] = make_float4(y1, x1, y2, x2);
}

// -------- 5. pairwise IoU bitmask — upper triangle only -----------------------
// Suppression in ordered NMS is forward-only: row i's words for col-blocks
// strictly before i's own word are never read by the sweep => skip them.
__global__ void iou_kernel() {
    int b = blockIdx.z;
    int C = blockIdx.x * 64;           // column start
    int R = blockIdx.y * 256;          // row start
    __shared__ float4 colBox[64];
    int tid = threadIdx.x;
    int ncols = min(64, TOPK - C);
    if (tid < ncols)
        colBox[tid] = reinterpret_cast<const float4*>(g_boxes)[b * TOPK + C + tid];
    __syncthreads();
    int i = R + tid;
    if (i >= TOPK || i >= C + 64) return;   // lower triangle: word never read
    float4 rb = reinterpret_cast<const float4*>(g_boxes)[b * TOPK + i];
    float area1 = (rb.z - rb.x) * (rb.w - rb.y);
    unsigned long long m = 0;
    for (int j = 0; j < ncols; ++j) {
        float4 cb = colBox[j];
        float y1 = fmaxf(rb.x, cb.x);
        float x1 = fmaxf(rb.y, cb.y);
        float y2 = fminf(rb.z, cb.z);
        float x2 = fminf(rb.w, cb.w);
        float inter = fmaxf(y2 - y1, 0.f) * fmaxf(x2 - x1, 0.f);
        float area2 = (cb.z - cb.x) * (cb.w - cb.y);
        float iou = inter / (area1 + area2 - inter + 1e-9f);
        if (iou > THR) m |= 1ull << j;
    }
    g_mask[((size_t)(b * TOPK + i)) * COLB + blockIdx.x] = m;
    if ((i >> 6) == (C >> 6))
        g_diag[b * TOPK + i] = m;          // row i's own word, for the fast chain
}

// -------- 6. two-phase sweep: smem-only chain + batched row ORs ---------------
__global__ void sweep_kernel(float* __restrict__ out) {
    extern __shared__ unsigned long long dsm[];
    unsigned long long* diag_sh = dsm;                 // TOPK u64 (48 KB)
    unsigned long long* rem_sh  = dsm + TOPK;          // COLB u64
    int* kept_sh = reinterpret_cast<int*>(rem_sh + COLB);  // NOUT ints
    int* ctrl    = kept_sh + NOUT;                     // [0]=m this word, [1]=cnt

    int b = blockIdx.x;
    int tid = threadIdx.x;
    for (int i = tid; i < TOPK; i += blockDim.x)
        diag_sh[i] = g_diag[b * TOPK + i];
    if (tid < COLB)
        rem_sh[tid] = (tid == COLB - 1) ? ~((1ull << TAIL_BITS) - 1ull) : 0ull;
    if (tid == 0) ctrl[1] = 0;
    __syncthreads();

    if (tid < 32) {
        int cnt = 0;
        for (int w = 0; w < COLB && cnt < NOUT; ++w) {
            // Phase A (lane 0): decide all kept bits of word w using only smem.
            // rem_sh[w] already holds suppressions from all earlier-word keeps;
            // within-word suppression comes from diag_sh.
            if (tid == 0) {
                unsigned long long avail = ~rem_sh[w];
                int m = 0;
                while (avail && cnt + m < NOUT) {
                    int bit = __ffsll((long long)avail) - 1;
                    int i = (w << 6) + bit;
                    kept_sh[cnt + m] = i;
                    ++m;
                    avail &= avail - 1;        // clear taken bit (zero-area safe)
                    avail &= ~diag_sh[i];      // within-word forward suppression
                }
                ctrl[0] = m;
            }
            __syncwarp();
            int m = ctrl[0];
            // Phase B (whole warp): OR kept rows into rem for words > w only.
            // Loads across k are independent -> full MLP, one latency per word.
            for (int k = 0; k < m; ++k) {
                const unsigned long long* row =
                    &g_mask[((size_t)(b * TOPK + kept_sh[cnt + k])) * COLB];
                for (int ww = w + 1 + tid; ww < COLB; ww += 32)
                    atomicOr(&rem_sh[ww], row[ww]);
            }
            cnt += m;
            __syncwarp();
        }
        if (tid == 0) ctrl[1] = cnt;
    }
    __syncthreads();

    int kc = ctrl[1];
    for (int k = tid; k < NOUT; k += blockDim.x) {
        float4 v = make_float4(0.f, 0.f, 0.f, 0.f);
        if (k < kc)
            v = reinterpret_cast<const float4*>(g_boxes)[b * TOPK + kept_sh[k]];
        reinterpret_cast<float4*>(out)[b * NOUT + k] = v;
    }
}

// -------- launch --------------------------------------------------------------
extern "C" void kernel_launch(void* const* d_in, const int* in_sizes, int n_in,
                              void* d_out, int out_size) {
    const float* rpn_class = (const float*)d_in[0];
    const float* rpn_bbox  = (const float*)d_in[1];
    const float* anchors   = (const float*)d_in[2];
    float* out = (float*)d_out;

    void *histp, *cntp, *candp, *sortedp, *offp, *tmpp;
    cudaGetSymbolAddress(&histp,   g_hist);
    cudaGetSymbolAddress(&cntp,    g_cnt);
    cudaGetSymbolAddress(&candp,   g_cand);
    cudaGetSymbolAddress(&sortedp, g_sorted);
    cudaGetSymbolAddress(&offp,    g_segoff);
    cudaGetSymbolAddress(&tmpp,    g_temp);

    cudaMemsetAsync(histp, 0, sizeof(g_hist));
    cudaMemsetAsync(cntp,  0, sizeof(g_cnt));
    cudaMemsetAsync(candp, 0, sizeof(g_cand));   // zero keys sort to segment end

    hist_kernel<<<TOTAL / 256, 256>>>((const float2*)rpn_class);
    thresh_kernel<<<BATCH, 256>>>();
    compact_kernel<<<TOTAL / 256, 256>>>((const float2*)rpn_class);

    size_t temp_bytes = 0;
    cub::DeviceSegmentedRadixSort::SortKeysDescending(
        nullptr, temp_bytes,
        (const unsigned long long*)candp, (unsigned long long*)sortedp,
        BATCH * CAP, BATCH,
        (const int*)offp, ((const int*)offp) + 1, 0, 48);
    if (temp_bytes <= sizeof(g_temp)) {
        cub::DeviceSegmentedRadixSort::SortKeysDescending(
            tmpp, temp_bytes,
            (const unsigned long long*)candp, (unsigned long long*)sortedp,
            BATCH * CAP, BATCH,
            (const int*)offp, ((const int*)offp) + 1, 0, 48);
    }

    boxes_kernel<<<(BATCH * TOPK + 255) / 256, 256>>>(rpn_bbox, anchors);

    dim3 gmask(COLB, (TOPK + 255) / 256, BATCH);
    iou_kernel<<<gmask, 256>>>();

    cudaFuncSetAttribute(sweep_kernel,
                         cudaFuncAttributeMaxDynamicSharedMemorySize, SWEEP_SMEM);
    sweep_kernel<<<BATCH, 128, SWEEP_SMEM>>>(out);
}

// round 7
// speedup vs baseline: 2.3137x; 2.3137x over previous
#include <cuda_runtime.h>
#include <cub/cub.cuh>
#include <cstdint>

namespace {
constexpr int BATCH = 8;
constexpr int NANCH = 262144;         // 2^18
constexpr int TOTAL = BATCH * NANCH;  // 2,097,152
constexpr int TOPK  = 6000;
constexpr int NOUT  = 1000;
constexpr int COLB  = (TOPK + 63) / 64;            // 94
constexpr float THR = 0.7f;
constexpr int TAIL_BITS = TOPK - (COLB - 1) * 64;  // 48
constexpr int HBINS = 32768;   // bucket = float_bits >> 15 (scores in (0,1))
constexpr int CAP   = 16384;   // per-batch candidate capacity (expected ~6400)
constexpr int SWEEP_THREADS = 256;
constexpr int SWEEP_SMEM = TOPK * 8 + COLB * 8 + NOUT * 4 + 16;
}

// -------- device-global scratch (no allocation allowed) ----------------------
__device__ int                g_hist[BATCH * HBINS];
__device__ int                g_thresh[BATCH];
__device__ int                g_cnt[BATCH];
__device__ unsigned long long g_cand  [BATCH * CAP];
__device__ unsigned long long g_sorted[BATCH * CAP];
__device__ int                g_segoff[BATCH + 1] =
    {0, CAP, 2*CAP, 3*CAP, 4*CAP, 5*CAP, 6*CAP, 7*CAP, 8*CAP};
__device__ __align__(16) float g_boxes[BATCH * TOPK * 4];
__device__ unsigned long long g_mask[(size_t)BATCH * TOPK * COLB];  // upper-tri valid
__device__ unsigned long long g_diag[BATCH * TOPK];
__device__ unsigned char      g_temp[16 * 1024 * 1024];             // cub temp

// -------- 1. per-batch histogram of score buckets ----------------------------
__global__ void hist_kernel(const float2* __restrict__ cls) {
    int g = blockIdx.x * blockDim.x + threadIdx.x;
    if (g >= TOTAL) return;
    float s = cls[g].y;                      // rpn_class[:,:,1], softmax > 0
    int bucket = (int)(__float_as_uint(s) >> 15);
    atomicAdd(&g_hist[(g >> 18) * HBINS + bucket], 1);
}

// -------- 2. threshold bucket: largest T with count(bucket >= T) >= TOPK -----
__global__ void thresh_kernel() {
    constexpr int BPT = HBINS / 256;
    int b = blockIdx.x;
    int t = threadIdx.x;
    __shared__ int lsum[256];
    __shared__ int suff[256];
    int base = b * HBINS + t * BPT;
    int s = 0;
    for (int i = 0; i < BPT; ++i) s += g_hist[base + i];
    lsum[t] = s;
    __syncthreads();
    if (t == 0) {
        int run = 0;
        for (int u = 255; u >= 0; --u) { suff[u] = run; run += lsum[u]; }
    }
    __syncthreads();
    int above = suff[t];
    if (above < TOPK && above + lsum[t] >= TOPK) {
        int run = above;
        for (int i = BPT - 1; i >= 0; --i) {
            run += g_hist[base + i];
            if (run >= TOPK) { g_thresh[b] = t * BPT + i; break; }
        }
    }
}

// -------- 3. compact candidates with composite key ----------------------------
__global__ void compact_kernel(const float2* __restrict__ cls) {
    int g = blockIdx.x * blockDim.x + threadIdx.x;
    if (g >= TOTAL) return;
    unsigned int bits = __float_as_uint(cls[g].y);
    int b = g >> 18;
    if ((int)(bits >> 15) >= __ldg(&g_thresh[b])) {
        int pos = atomicAdd(&g_cnt[b], 1);
        if (pos < CAP)
            g_cand[b * CAP + pos] =
                ((unsigned long long)bits << 18) |
                (unsigned long long)(0x3FFFF - (g & (NANCH - 1)));
    }
}

// -------- 4. gather top-6000, apply deltas, clip ------------------------------
__global__ void boxes_kernel(const float* __restrict__ rpn_bbox,
                             const float* __restrict__ anchors) {
    int t = blockIdx.x * blockDim.x + threadIdx.x;
    if (t >= BATCH * TOPK) return;
    int b = t / TOPK;
    int k = t - b * TOPK;
    unsigned long long key = g_sorted[b * CAP + k];
    int idx = 0x3FFFF - (int)(key & 0x3FFFFull);
    int src = (b * NANCH + idx) * 4;
    float4 a = *reinterpret_cast<const float4*>(anchors  + src);
    float4 d = *reinterpret_cast<const float4*>(rpn_bbox + src);
    float dy = d.x * 0.1f, dx = d.y * 0.1f;
    float dh = d.z * 0.2f, dw = d.w * 0.2f;
    float h = a.z - a.x;
    float w = a.w - a.y;
    float cy = a.x + 0.5f * h;
    float cx = a.y + 0.5f * w;
    cy = cy + dy * h;
    cx = cx + dx * w;
    h = h * expf(dh);
    w = w * expf(dw);
    float y1 = fminf(fmaxf(cy - 0.5f * h, 0.f), 1.f);
    float x1 = fminf(fmaxf(cx - 0.5f * w, 0.f), 1.f);
    float y2 = fminf(fmaxf(cy + 0.5f * h, 0.f), 1.f);
    float x2 = fminf(fmaxf(cx + 0.5f * w, 0.f), 1.f);
    reinterpret_cast<float4*>(g_boxes)[t] = make_float4(y1, x1, y2, x2);
}

// -------- 5. pairwise IoU bitmask — upper triangle, 2-pass overlap filter ------
// Pass 1: cheap separating-axis test per col -> candidate bitmask (exact: no
// overlap => inter == 0 => iou == 0 < THR). Pass 2: exact fp32 IoU only on
// candidate bits (~10% of pairs carry the expensive division).
__global__ void iou_kernel() {
    int b = blockIdx.z;
    int C = blockIdx.x * 64;           // column start
    int R = blockIdx.y * 256;          // row start
    if (R >= C + 64) return;           // whole block below diagonal: never read
    __shared__ float4 colBox[64];
    int tid = threadIdx.x;
    int ncols = min(64, TOPK - C);
    if (tid < ncols)
        colBox[tid] = reinterpret_cast<const float4*>(g_boxes)[b * TOPK + C + tid];
    __syncthreads();
    int i = R + tid;
    if (i >= TOPK || i >= C + 64) return;
    float4 rb = reinterpret_cast<const float4*>(g_boxes)[b * TOPK + i];
    float area1 = (rb.z - rb.x) * (rb.w - rb.y);

    unsigned long long cand = 0;
    #pragma unroll 4
    for (int j = 0; j < ncols; ++j) {
        float4 cb = colBox[j];
        float dy = fminf(rb.z, cb.z) - fmaxf(rb.x, cb.x);
        float dx = fminf(rb.w, cb.w) - fmaxf(rb.y, cb.y);
        if (dy > 0.f && dx > 0.f) cand |= 1ull << j;
    }

    unsigned long long m = 0;
    while (cand) {
        int j = __ffsll((long long)cand) - 1;
        cand &= cand - 1;
        float4 cb = colBox[j];
        float y1 = fmaxf(rb.x, cb.x);
        float x1 = fmaxf(rb.y, cb.y);
        float y2 = fminf(rb.z, cb.z);
        float x2 = fminf(rb.w, cb.w);
        float inter = fmaxf(y2 - y1, 0.f) * fmaxf(x2 - x1, 0.f);
        float area2 = (cb.z - cb.x) * (cb.w - cb.y);
        float iou = inter / (area1 + area2 - inter + 1e-9f);
        if (iou > THR) m |= 1ull << j;
    }
    g_mask[((size_t)(b * TOPK + i)) * COLB + blockIdx.x] = m;
    if ((i >> 6) == (C >> 6))
        g_diag[b * TOPK + i] = m;          // row i's own word, for the fast chain
}

// -------- 6. sweep: smem chain (thread 0) + BLOCK-parallel batched row ORs -----
__global__ void __launch_bounds__(SWEEP_THREADS)
sweep_kernel(float* __restrict__ out) {
    extern __shared__ unsigned long long dsm[];
    unsigned long long* diag_sh = dsm;                 // TOPK u64 (48 KB)
    unsigned long long* rem_sh  = dsm + TOPK;          // COLB u64
    int* kept_sh = reinterpret_cast<int*>(rem_sh + COLB);  // NOUT ints
    int* ctrl    = kept_sh + NOUT;                     // [0]=m for this word

    int b = blockIdx.x;
    int tid = threadIdx.x;
    int warp = tid >> 5;
    int lane = tid & 31;
    constexpr int NWARP = SWEEP_THREADS / 32;

    for (int i = tid; i < TOPK; i += SWEEP_THREADS)
        diag_sh[i] = g_diag[b * TOPK + i];
    if (tid < COLB)
        rem_sh[tid] = (tid == COLB - 1) ? ~((1ull << TAIL_BITS) - 1ull) : 0ull;
    __syncthreads();

    int cnt = 0;
    for (int w = 0; w < COLB; ++w) {
        // Phase A (thread 0): resolve all kept bits of word w using smem only.
        if (tid == 0) {
            unsigned long long avail = ~rem_sh[w];
            int m = 0;
            while (avail && cnt + m < NOUT) {
                int bit = __ffsll((long long)avail) - 1;
                int i = (w << 6) + bit;
                kept_sh[cnt + m] = i;
                ++m;
                avail &= avail - 1;        // clear taken bit (zero-area safe)
                avail &= ~diag_sh[i];      // within-word forward suppression
            }
            ctrl[0] = m;
        }
        __syncthreads();
        int m = ctrl[0];
        // Phase B (whole block): OR the m kept rows into rem for words > w.
        // warps split k, lanes split ww -> all LDGs independent, ~1 latency/word.
        for (int k = warp; k < m; k += NWARP) {
            const unsigned long long* row =
                &g_mask[((size_t)(b * TOPK + kept_sh[cnt + k])) * COLB];
            for (int ww = w + 1 + lane; ww < COLB; ww += 32)
                atomicOr(&rem_sh[ww], row[ww]);
        }
        cnt += m;
        if (cnt >= NOUT) break;           // uniform across block: safe
        __syncthreads();
    }
    __syncthreads();

    for (int k = tid; k < NOUT; k += SWEEP_THREADS) {
        float4 v = make_float4(0.f, 0.f, 0.f, 0.f);
        if (k < cnt)
            v = reinterpret_cast<const float4*>(g_boxes)[b * TOPK + kept_sh[k]];
        reinterpret_cast<float4*>(out)[b * NOUT + k] = v;
    }
}

// -------- launch --------------------------------------------------------------
extern "C" void kernel_launch(void* const* d_in, const int* in_sizes, int n_in,
                              void* d_out, int out_size) {
    const float* rpn_class = (const float*)d_in[0];
    const float* rpn_bbox  = (const float*)d_in[1];
    const float* anchors   = (const float*)d_in[2];
    float* out = (float*)d_out;

    void *histp, *cntp, *candp, *sortedp, *offp, *tmpp;
    cudaGetSymbolAddress(&histp,   g_hist);
    cudaGetSymbolAddress(&cntp,    g_cnt);
    cudaGetSymbolAddress(&candp,   g_cand);
    cudaGetSymbolAddress(&sortedp, g_sorted);
    cudaGetSymbolAddress(&offp,    g_segoff);
    cudaGetSymbolAddress(&tmpp,    g_temp);

    cudaMemsetAsync(histp, 0, sizeof(g_hist));
    cudaMemsetAsync(cntp,  0, sizeof(g_cnt));
    cudaMemsetAsync(candp, 0, sizeof(g_cand));   // zero keys sort to segment end

    hist_kernel<<<TOTAL / 256, 256>>>((const float2*)rpn_class);
    thresh_kernel<<<BATCH, 256>>>();
    compact_kernel<<<TOTAL / 256, 256>>>((const float2*)rpn_class);

    size_t temp_bytes = 0;
    cub::DeviceSegmentedRadixSort::SortKeysDescending(
        nullptr, temp_bytes,
        (const unsigned long long*)candp, (unsigned long long*)sortedp,
        BATCH * CAP, BATCH,
        (const int*)offp, ((const int*)offp) + 1, 0, 48);
    if (temp_bytes <= sizeof(g_temp)) {
        cub::DeviceSegmentedRadixSort::SortKeysDescending(
            tmpp, temp_bytes,
            (const unsigned long long*)candp, (unsigned long long*)sortedp,
            BATCH * CAP, BATCH,
            (const int*)offp, ((const int*)offp) + 1, 0, 48);
    }

    boxes_kernel<<<(BATCH * TOPK + 255) / 256, 256>>>(rpn_bbox, anchors);

    dim3 gmask(COLB, (TOPK + 255) / 256, BATCH);
    iou_kernel<<<gmask, 256>>>();

    cudaFuncSetAttribute(sweep_kernel,
                         cudaFuncAttributeMaxDynamicSharedMemorySize, SWEEP_SMEM);
    sweep_kernel<<<BATCH, SWEEP_THREADS, SWEEP_SMEM>>>(out);
}